// round 4
// baseline (speedup 1.0000x reference)
#include <cuda_runtime.h>

// LinearAttention per (b,l) site (16384 sites):
//   qf=elu(q)+1, kf=elu(k)+1 [32,64]; A = qf@kf^T [32,32];
//   y[h] = L^-0.5/(rowsum(A)+eps); x = diag(y) A V [32,64].
// R4: 7 CTAs/SM via smem overlays, balanced per-warp epilogues
//     (each warp finalizes 16 rows of A and 16 rows of X), y folded into A.

#define HH 32
#define EE 64
#define DD 64
#define RP 68       // q/k pitch (272B) -> stage-1 rows conflict-free
#define VP 64       // v pitch (256B)  -> stage-2 reads broadcast within 128B
#define AP 36       // A pitch (144B)
#define P1 20       // stage-1 partial pitch (floats, 80B)
#define P2 18       // stage-2 partial pitch (u64, 144B)
#define EPSV 1e-6f
#define RSQRT_L 0.022097086912079608f   // 2048^-0.5

typedef unsigned long long u64;

__device__ __forceinline__ u64 f2fma(u64 a, u64 b, u64 c) {
    u64 d;
    asm("fma.rn.f32x2 %0, %1, %2, %3;" : "=l"(d) : "l"(a), "l"(b), "l"(c));
    return d;
}
__device__ __forceinline__ u64 f2add(u64 a, u64 b) {
    u64 d;
    asm("add.rn.f32x2 %0, %1, %2;" : "=l"(d) : "l"(a), "l"(b));
    return d;
}
__device__ __forceinline__ u64 pk2(float lo, float hi) {
    u64 r;
    asm("mov.b64 %0, {%1, %2};" : "=l"(r) : "f"(lo), "f"(hi));
    return r;
}
__device__ __forceinline__ float2 unpk(u64 v) {
    float2 r;
    asm("mov.b64 {%0, %1}, %2;" : "=f"(r.x), "=f"(r.y) : "l"(v));
    return r;
}
__device__ __forceinline__ float foldp(u64 v) {
    float2 t = unpk(v);
    return t.x + t.y;
}
__device__ __forceinline__ float elu1(float x) {
    float r;
    asm("ex2.approx.ftz.f32 %0, %1;" : "=f"(r) : "f"(x * 1.4426950408889634f));
    return x > 0.0f ? x + 1.0f : r;
}

__global__ void __launch_bounds__(64, 7) linattn_kernel(
    const float* __restrict__ Q, const float* __restrict__ K,
    const float* __restrict__ V, float* __restrict__ O)
{
    // sQ/sK are reused after stage-1 compute as partial-exchange buffers:
    //   w1's publishes live in sQ-space, w0's publishes live in sK-space.
    __shared__ __align__(16) float sQ[HH * RP];   // 8704 B
    __shared__ __align__(16) float sK[HH * RP];   // 8704 B
    __shared__ __align__(16) float sV[HH * VP];   // 8192 B
    __shared__ __align__(16) float sA[HH * AP];   // 4608 B  -> total 30208 B

    const int tid = threadIdx.x;
    const int w   = tid >> 5;       // warp 0/1
    const int ln  = tid & 31;
    const size_t site = blockIdx.x;

    const float4* q4 = (const float4*)(Q + site * (HH * EE));
    const float4* k4 = (const float4*)(K + site * (HH * EE));
    const float4* v4 = (const float4*)(V + site * (HH * DD));

    // ---- Load + elu+1 (q,k), raw copy (v). 512 float4s, 64 threads. ----
    #pragma unroll
    for (int it = 0; it < 8; ++it) {
        int f  = tid + it * 64;       // 0..511
        int h  = f >> 4;
        int e4 = (f & 15) << 2;
        float4 a = q4[f];
        a.x = elu1(a.x); a.y = elu1(a.y); a.z = elu1(a.z); a.w = elu1(a.w);
        *(float4*)&sQ[h * RP + e4] = a;
        float4 b = k4[f];
        b.x = elu1(b.x); b.y = elu1(b.y); b.z = elu1(b.z); b.w = elu1(b.w);
        *(float4*)&sK[h * RP + e4] = b;
        *(float4*)&sV[h * VP + e4] = v4[f];
    }
    __syncthreads();                                  // bar0

    // ================= Stage 1: A = qf @ kf^T, split-K by warp =========
    // warp w covers e in [32w, 32w+32). Lane tile: rows {rg+8i}, cols {cg+4j}.
    const int rg = ln & 7;
    const int cg = ln >> 3;
    {
        const int eb = 32 * w;
        u64 acc[4][8];
        #pragma unroll
        for (int i = 0; i < 4; ++i)
            #pragma unroll
            for (int j = 0; j < 8; ++j) acc[i][j] = 0ULL;

        #pragma unroll
        for (int c = 0; c < 8; ++c) {
            int e0 = eb + 4 * c;
            ulonglong2 qv[4];
            #pragma unroll
            for (int i = 0; i < 4; ++i)
                qv[i] = *(const ulonglong2*)&sQ[(rg + 8 * i) * RP + e0];
            #pragma unroll
            for (int j = 0; j < 8; ++j) {
                ulonglong2 kv = *(const ulonglong2*)&sK[(cg + 4 * j) * RP + e0];
                #pragma unroll
                for (int i = 0; i < 4; ++i) {
                    acc[i][j] = f2fma(qv[i].x, kv.x, acc[i][j]);
                    acc[i][j] = f2fma(qv[i].y, kv.y, acc[i][j]);
                }
            }
        }

        __syncthreads();                              // bar1: sQ/sK now dead

        // w0 finalizes rows 0-15 (i=0,1) and publishes i=2,3 into sK-space.
        // w1 finalizes rows 16-31 (i=2,3) and publishes i=0,1 into sQ-space.
        float* mypub = (w == 0) ? sK : sQ;
        const float* otpub = (w == 0) ? sQ : sK;
        const int ipub = (w == 0) ? 2 : 0;   // my published i-range start
        const int ifin = (w == 0) ? 0 : 2;   // my finalized i-range start

        #pragma unroll
        for (int ii = 0; ii < 2; ++ii) {
            int i = ipub + ii;
            float4 p0, p1;
            p0.x = foldp(acc[i][0]); p0.y = foldp(acc[i][1]);
            p0.z = foldp(acc[i][2]); p0.w = foldp(acc[i][3]);
            p1.x = foldp(acc[i][4]); p1.y = foldp(acc[i][5]);
            p1.z = foldp(acc[i][6]); p1.w = foldp(acc[i][7]);
            *(float4*)&mypub[ln * P1 + ii * 8]     = p0;
            *(float4*)&mypub[ln * P1 + ii * 8 + 4] = p1;
        }
        __syncthreads();                              // bar2: partials visible

        #pragma unroll
        for (int ii = 0; ii < 2; ++ii) {
            int i = ifin + ii;
            int row = rg + 8 * i;
            float4 o0 = *(const float4*)&otpub[ln * P1 + ii * 8];
            float4 o1 = *(const float4*)&otpub[ln * P1 + ii * 8 + 4];
            float f[8];
            f[0] = foldp(acc[i][0]) + o0.x;  f[1] = foldp(acc[i][1]) + o0.y;
            f[2] = foldp(acc[i][2]) + o0.z;  f[3] = foldp(acc[i][3]) + o0.w;
            f[4] = foldp(acc[i][4]) + o1.x;  f[5] = foldp(acc[i][5]) + o1.y;
            f[6] = foldp(acc[i][6]) + o1.z;  f[7] = foldp(acc[i][7]) + o1.w;
            float s = ((f[0] + f[1]) + (f[2] + f[3]))
                    + ((f[4] + f[5]) + (f[6] + f[7]));
            s += __shfl_xor_sync(0xffffffffu, s, 8);
            s += __shfl_xor_sync(0xffffffffu, s, 16);
            float y = RSQRT_L / (s + EPSV);
            #pragma unroll
            for (int j = 0; j < 8; ++j)
                sA[row * AP + cg + 4 * j] = y * f[j];   // conflict-free scalar STS
        }
    }
    __syncthreads();                                  // bar3: A' complete

    // ================= Stage 2: X = A' @ V, split-h' by warp ============
    // warp w covers h' in [16w, 16w+16). Lane tile: rows {rg2+4i}, d {4dg..+3, +32}.
    {
        const int rg2 = ln & 3;
        const int dg  = ln >> 2;
        const int hb  = 16 * w;

        u64 xa[8][4];
        #pragma unroll
        for (int i = 0; i < 8; ++i)
            #pragma unroll
            for (int k = 0; k < 4; ++k) xa[i][k] = 0ULL;

        #pragma unroll
        for (int hc = 0; hc < 4; ++hc) {
            float4 av[8];
            #pragma unroll
            for (int i = 0; i < 8; ++i)
                av[i] = *(const float4*)&sA[(rg2 + 4 * i) * AP + hb + 4 * hc];
            #pragma unroll
            for (int u = 0; u < 4; ++u) {
                int hh = hb + 4 * hc + u;
                ulonglong2 v0 = *(const ulonglong2*)&sV[hh * VP + 4 * dg];
                ulonglong2 v1 = *(const ulonglong2*)&sV[hh * VP + 4 * dg + 32];
                #pragma unroll
                for (int i = 0; i < 8; ++i) {
                    float s  = (u == 0) ? av[i].x : (u == 1) ? av[i].y
                             : (u == 2) ? av[i].z : av[i].w;
                    u64 ps = pk2(s, s);
                    xa[i][0] = f2fma(ps, v0.x, xa[i][0]);
                    xa[i][1] = f2fma(ps, v0.y, xa[i][1]);
                    xa[i][2] = f2fma(ps, v1.x, xa[i][2]);
                    xa[i][3] = f2fma(ps, v1.y, xa[i][3]);
                }
            }
        }

        // w0 finalizes rows 0-15 (i=0..3), publishes i=4..7 into sK-space.
        // w1 finalizes rows 16-31 (i=4..7), publishes i=0..3 into sQ-space.
        // (No bar before publish: stage-2 compute reads only sA/sV; the last
        //  readers of sQ/sK-space ran before bar3.)
        u64* mypub2 = (w == 0) ? (u64*)sK : (u64*)sQ;
        const u64* otpub2 = (w == 0) ? (const u64*)sQ : (const u64*)sK;
        const int ipub2 = (w == 0) ? 4 : 0;
        const int ifin2 = (w == 0) ? 0 : 4;

        #pragma unroll
        for (int ii = 0; ii < 4; ++ii) {
            int i = ipub2 + ii;
            *(ulonglong2*)&mypub2[ln * P2 + ii * 4]     = *(ulonglong2*)&xa[i][0];
            *(ulonglong2*)&mypub2[ln * P2 + ii * 4 + 2] = *(ulonglong2*)&xa[i][2];
        }
        __syncthreads();                              // bar4: partials visible

        float* ob = O + site * (size_t)(HH * DD);
        #pragma unroll
        for (int ii = 0; ii < 4; ++ii) {
            int i = ifin2 + ii;
            int row = rg2 + 4 * i;
            ulonglong2 oa = *(const ulonglong2*)&otpub2[ln * P2 + ii * 4];
            ulonglong2 obx = *(const ulonglong2*)&otpub2[ln * P2 + ii * 4 + 2];
            ulonglong2 w0, w1;
            w0.x = f2add(xa[i][0], oa.x);
            w0.y = f2add(xa[i][1], oa.y);
            w1.x = f2add(xa[i][2], obx.x);
            w1.y = f2add(xa[i][3], obx.y);
            *(ulonglong2*)(ob + row * DD + 4 * dg)      = w0;
            *(ulonglong2*)(ob + row * DD + 4 * dg + 32) = w1;
        }
    }
}

extern "C" void kernel_launch(void* const* d_in, const int* in_sizes, int n_in,
                              void* d_out, int out_size) {
    const float* Q = (const float*)d_in[0];
    const float* K = (const float*)d_in[1];
    const float* V = (const float*)d_in[2];
    float* O = (float*)d_out;
    int nsites = in_sizes[0] / (HH * EE);   // B*L = 16384
    linattn_kernel<<<nsites, 64>>>(Q, K, V, O);
}

// round 5
// speedup vs baseline: 1.3970x; 1.3970x over previous
#include <cuda_runtime.h>

// LinearAttention per (b,l) site (16384 sites):
//   qf=elu(q)+1, kf=elu(k)+1 [32,64]; A = qf@kf^T [32,32];
//   y[h] = L^-0.5/(rowsum(A)+eps); x = diag(y) A V [32,64].
// R5: R3 structure (proven 142 regs, no spills) with smem shrunk to exactly
//     32 KB (sV pitch 64, tight partial buffers, stage-2 exchange overlaid
//     on dead sQ) -> 7 CTAs/SM instead of 6.

#define HH 32
#define EE 64
#define DD 64
#define RP 68       // q/k pitch (272B): stage-1 row accesses conflict-free
#define VP 64       // v pitch (256B): stage-2 reads stride 16B -> conflict-free
#define AP 36       // A pitch (144B)
#define P1 20       // stage-1 partial pitch (floats, 80B stride -> conflict-free)
#define P2 18       // stage-2 partial pitch (u64, 144B stride -> conflict-free)
#define EPSV 1e-6f
#define RSQRT_L 0.022097086912079608f   // 2048^-0.5

typedef unsigned long long u64;

__device__ __forceinline__ u64 f2fma(u64 a, u64 b, u64 c) {
    u64 d;
    asm("fma.rn.f32x2 %0, %1, %2, %3;" : "=l"(d) : "l"(a), "l"(b), "l"(c));
    return d;
}
__device__ __forceinline__ u64 f2add(u64 a, u64 b) {
    u64 d;
    asm("add.rn.f32x2 %0, %1, %2;" : "=l"(d) : "l"(a), "l"(b));
    return d;
}
__device__ __forceinline__ u64 f2mul(u64 a, u64 b) {
    u64 d;
    asm("mul.rn.f32x2 %0, %1, %2;" : "=l"(d) : "l"(a), "l"(b));
    return d;
}
__device__ __forceinline__ u64 pk2(float lo, float hi) {
    u64 r;
    asm("mov.b64 %0, {%1, %2};" : "=l"(r) : "f"(lo), "f"(hi));
    return r;
}
__device__ __forceinline__ float2 unpk(u64 v) {
    float2 r;
    asm("mov.b64 {%0, %1}, %2;" : "=f"(r.x), "=f"(r.y) : "l"(v));
    return r;
}
__device__ __forceinline__ float foldp(u64 v) {
    float2 t = unpk(v);
    return t.x + t.y;
}
__device__ __forceinline__ float elu1(float x) {
    float r;
    asm("ex2.approx.ftz.f32 %0, %1;" : "=f"(r) : "f"(x * 1.4426950408889634f));
    return x > 0.0f ? x + 1.0f : r;
}

__global__ void __launch_bounds__(64, 6) linattn_kernel(
    const float* __restrict__ Q, const float* __restrict__ K,
    const float* __restrict__ V, float* __restrict__ O)
{
    __shared__ __align__(16) float sQ[HH * RP];   // 8704 B (reused: stage-2 partials)
    __shared__ __align__(16) float sK[HH * RP];   // 8704 B
    __shared__ __align__(16) float sV[HH * VP];   // 8192 B
    __shared__ __align__(16) float sA[HH * AP];   // 4608 B
    __shared__ __align__(16) float sP1[HH * P1];  // 2560 B  -> total 32768 B

    const int tid = threadIdx.x;
    const int w   = tid >> 5;       // warp 0/1
    const int ln  = tid & 31;
    const size_t site = blockIdx.x;

    const float4* q4 = (const float4*)(Q + site * (HH * EE));
    const float4* k4 = (const float4*)(K + site * (HH * EE));
    const float4* v4 = (const float4*)(V + site * (HH * DD));

    // ---- Load + elu+1 (q,k), raw copy (v). 512 float4s, 64 threads. ----
    #pragma unroll
    for (int it = 0; it < 8; ++it) {
        int f  = tid + it * 64;       // 0..511
        int h  = f >> 4;
        int e4 = (f & 15) << 2;
        float4 a = q4[f];
        a.x = elu1(a.x); a.y = elu1(a.y); a.z = elu1(a.z); a.w = elu1(a.w);
        *(float4*)&sQ[h * RP + e4] = a;
        float4 b = k4[f];
        b.x = elu1(b.x); b.y = elu1(b.y); b.z = elu1(b.z); b.w = elu1(b.w);
        *(float4*)&sK[h * RP + e4] = b;
        *(float4*)&sV[h * VP + e4] = v4[f];
    }
    __syncthreads();

    // ================= Stage 1: A = qf @ kf^T, split-K by warp =========
    // warp w covers e in [32w, 32w+32). Lane tile: rows {rg+8i}, cols {cg+4j}.
    {
        const int rg = ln & 7;
        const int cg = ln >> 3;
        const int eb = 32 * w;

        u64 acc[4][8];
        #pragma unroll
        for (int i = 0; i < 4; ++i)
            #pragma unroll
            for (int j = 0; j < 8; ++j) acc[i][j] = 0ULL;

        #pragma unroll
        for (int c = 0; c < 8; ++c) {
            int e0 = eb + 4 * c;
            ulonglong2 qv[4];
            #pragma unroll
            for (int i = 0; i < 4; ++i)
                qv[i] = *(const ulonglong2*)&sQ[(rg + 8 * i) * RP + e0];
            #pragma unroll
            for (int j = 0; j < 8; ++j) {
                ulonglong2 kv = *(const ulonglong2*)&sK[(cg + 4 * j) * RP + e0];
                #pragma unroll
                for (int i = 0; i < 4; ++i) {
                    acc[i][j] = f2fma(qv[i].x, kv.x, acc[i][j]);
                    acc[i][j] = f2fma(qv[i].y, kv.y, acc[i][j]);
                }
            }
        }

        if (w == 1) {
            // fold e-pairs, publish f32 partials into dedicated sP1
            #pragma unroll
            for (int i = 0; i < 4; ++i) {
                float4 p0, p1;
                p0.x = foldp(acc[i][0]); p0.y = foldp(acc[i][1]);
                p0.z = foldp(acc[i][2]); p0.w = foldp(acc[i][3]);
                p1.x = foldp(acc[i][4]); p1.y = foldp(acc[i][5]);
                p1.z = foldp(acc[i][6]); p1.w = foldp(acc[i][7]);
                // two float4 stores per i would exceed P1=20; pack 8 floats per i
                // at offset 0/8/16 -> need 32 floats: use pitch layout [i*8+j]
                *(float4*)&sP1[ln * P1 + 0]  = p0;   // placeholder overwritten below
                *(float4*)&sP1[ln * P1 + 4]  = p1;
                // NOTE: loop rewritten below without placeholder
            }
        }
        // (rewrite publish cleanly: 32 floats don't fit pitch 20; split scheme)
        __syncthreads();   // sync1 (see corrected publish below)

        // ---- corrected exchange: two half-rounds of 16 floats each ----
        // Round A: w1 publishes i=0,1 ; w0 consumes -> finalizes rows of i=0,1.
        // Round B: w1 publishes i=2,3 ; w0 consumes -> finalizes rows of i=2,3.
        #pragma unroll
        for (int half = 0; half < 2; ++half) {
            if (w == 1) {
                #pragma unroll
                for (int ii = 0; ii < 2; ++ii) {
                    int i = half * 2 + ii;
                    float4 p0, p1;
                    p0.x = foldp(acc[i][0]); p0.y = foldp(acc[i][1]);
                    p0.z = foldp(acc[i][2]); p0.w = foldp(acc[i][3]);
                    p1.x = foldp(acc[i][4]); p1.y = foldp(acc[i][5]);
                    p1.z = foldp(acc[i][6]); p1.w = foldp(acc[i][7]);
                    *(float4*)&sP1[ln * P1 + ii * 8]     = p0;
                    *(float4*)&sP1[ln * P1 + ii * 8 + 4] = p1;
                }
            }
            __syncthreads();
            if (w == 0) {
                #pragma unroll
                for (int ii = 0; ii < 2; ++ii) {
                    int i = half * 2 + ii;
                    int row = rg + 8 * i;
                    float4 o0 = *(const float4*)&sP1[ln * P1 + ii * 8];
                    float4 o1 = *(const float4*)&sP1[ln * P1 + ii * 8 + 4];
                    sA[row * AP + cg]      = foldp(acc[i][0]) + o0.x;
                    sA[row * AP + cg + 4]  = foldp(acc[i][1]) + o0.y;
                    sA[row * AP + cg + 8]  = foldp(acc[i][2]) + o0.z;
                    sA[row * AP + cg + 12] = foldp(acc[i][3]) + o0.w;
                    sA[row * AP + cg + 16] = foldp(acc[i][4]) + o1.x;
                    sA[row * AP + cg + 20] = foldp(acc[i][5]) + o1.y;
                    sA[row * AP + cg + 24] = foldp(acc[i][6]) + o1.z;
                    sA[row * AP + cg + 28] = foldp(acc[i][7]) + o1.w;
                }
            }
            __syncthreads();
        }
    }

    // ---- warp0 computes y[ln] (held in register; shfl'd at epilogue) ----
    float yv = 0.0f;
    if (w == 0) {
        const float4* ar = (const float4*)&sA[ln * AP];
        float s = 0.0f;
        #pragma unroll
        for (int j = 0; j < HH / 4; ++j) {
            float4 t = ar[j];
            s += (t.x + t.y) + (t.z + t.w);
        }
        yv = RSQRT_L / (s + EPSV);
    }

    // ================= Stage 2: X = A @ V, split-H' by warp ============
    // warp w covers h' in [16w, 16w+16). Lane tile: rows {rg2+4i} (8 rows),
    // d in {4dg..4dg+3} and {4dg+32..4dg+35}.
    {
        const int rg2 = ln & 3;
        const int dg  = ln >> 2;
        const int hb  = 16 * w;
        u64* sP2 = (u64*)sQ;   // overlay on dead sQ (last read before sync1)

        u64 xa[8][4];
        #pragma unroll
        for (int i = 0; i < 8; ++i)
            #pragma unroll
            for (int k = 0; k < 4; ++k) xa[i][k] = 0ULL;

        #pragma unroll
        for (int hc = 0; hc < 4; ++hc) {
            float4 av[8];
            #pragma unroll
            for (int i = 0; i < 8; ++i)
                av[i] = *(const float4*)&sA[(rg2 + 4 * i) * AP + hb + 4 * hc];
            #pragma unroll
            for (int u = 0; u < 4; ++u) {
                int hh = hb + 4 * hc + u;
                ulonglong2 v0 = *(const ulonglong2*)&sV[hh * VP + 4 * dg];
                ulonglong2 v1 = *(const ulonglong2*)&sV[hh * VP + 4 * dg + 32];
                #pragma unroll
                for (int i = 0; i < 8; ++i) {
                    float s  = (u == 0) ? av[i].x : (u == 1) ? av[i].y
                             : (u == 2) ? av[i].z : av[i].w;
                    u64 ps = pk2(s, s);
                    xa[i][0] = f2fma(ps, v0.x, xa[i][0]);
                    xa[i][1] = f2fma(ps, v0.y, xa[i][1]);
                    xa[i][2] = f2fma(ps, v1.x, xa[i][2]);
                    xa[i][3] = f2fma(ps, v1.y, xa[i][3]);
                }
            }
        }

        if (w == 1) {
            #pragma unroll
            for (int i = 0; i < 8; ++i) {
                *(ulonglong2*)&sP2[ln * P2 + ((i & 3) * 4)]     // reuse rows: two
                    = *(ulonglong2*)&xa[i][0];                  //  passes below
                *(ulonglong2*)&sP2[ln * P2 + ((i & 3) * 4) + 2]
                    = *(ulonglong2*)&xa[i][2];
                // NOTE: pitch 18 holds 16 u64 (4 i-values). Exchange in halves.
                if (i == 3) { /* flush first half */ }
            }
        }
        // ---- corrected stage-2 exchange: two half-rounds (i=0..3, i=4..7) ----
        // (the loop above wrote only the second half's slots; redo cleanly)
        __syncthreads();

        float* ob = O + site * (size_t)(HH * DD);
        #pragma unroll
        for (int half = 0; half < 2; ++half) {
            if (w == 1) {
                #pragma unroll
                for (int ii = 0; ii < 4; ++ii) {
                    int i = half * 4 + ii;
                    *(ulonglong2*)&sP2[ln * P2 + ii * 4]     = *(ulonglong2*)&xa[i][0];
                    *(ulonglong2*)&sP2[ln * P2 + ii * 4 + 2] = *(ulonglong2*)&xa[i][2];
                }
            }
            __syncthreads();
            if (w == 0) {
                #pragma unroll
                for (int ii = 0; ii < 4; ++ii) {
                    int i = half * 4 + ii;
                    int row = rg2 + 4 * i;
                    float yi = __shfl_sync(0xffffffffu, yv, row);
                    u64 py = pk2(yi, yi);
                    ulonglong2 oa  = *(const ulonglong2*)&sP2[ln * P2 + ii * 4];
                    ulonglong2 obx = *(const ulonglong2*)&sP2[ln * P2 + ii * 4 + 2];
                    ulonglong2 w0v, w1v;
                    w0v.x = f2mul(f2add(xa[i][0], oa.x),  py);
                    w0v.y = f2mul(f2add(xa[i][1], oa.y),  py);
                    w1v.x = f2mul(f2add(xa[i][2], obx.x), py);
                    w1v.y = f2mul(f2add(xa[i][3], obx.y), py);
                    *(ulonglong2*)(ob + row * DD + 4 * dg)      = w0v;
                    *(ulonglong2*)(ob + row * DD + 4 * dg + 32) = w1v;
                }
            }
            __syncthreads();
        }
    }
}

extern "C" void kernel_launch(void* const* d_in, const int* in_sizes, int n_in,
                              void* d_out, int out_size) {
    const float* Q = (const float*)d_in[0];
    const float* K = (const float*)d_in[1];
    const float* V = (const float*)d_in[2];
    float* O = (float*)d_out;
    int nsites = in_sizes[0] / (HH * EE);   // B*L = 16384
    linattn_kernel<<<nsites, 64>>>(Q, K, V, O);
}

// round 6
// speedup vs baseline: 1.6390x; 1.1733x over previous
#include <cuda_runtime.h>

// LinearAttention per (b,l) site (16384 sites):
//   qf=elu(q)+1, kf=elu(k)+1 [32,64]; A = qf@kf^T [32,32];
//   y[h] = L^-0.5/(rowsum(A)+eps); x = diag(y) A V [32,64].
// R6: R3 compute structure (142-reg, no spills, single-round exchanges),
//     but partial-exchange buffers overlaid on dead sK (stage 1) and dead
//     sQ (stage 2). smem = 30208 B -> with the ~1KB/CTA driver tax, 7 CTAs/SM.

#define HH 32
#define EE 64
#define DD 64
#define RP 68       // q/k pitch (272B): stage-1 row accesses conflict-free
#define VP 64       // v pitch (256B): stage-2 reads stride 16B -> conflict-free
#define AP 36       // A pitch (144B)
#define PF1 36      // stage-1 partial pitch in sK-space (floats, 144B, 16B-aligned)
#define PU2 34      // stage-2 partial pitch in sQ-space (u64, 272B, 16B-aligned)
#define EPSV 1e-6f
#define RSQRT_L 0.022097086912079608f   // 2048^-0.5

typedef unsigned long long u64;

__device__ __forceinline__ u64 f2fma(u64 a, u64 b, u64 c) {
    u64 d;
    asm("fma.rn.f32x2 %0, %1, %2, %3;" : "=l"(d) : "l"(a), "l"(b), "l"(c));
    return d;
}
__device__ __forceinline__ u64 f2add(u64 a, u64 b) {
    u64 d;
    asm("add.rn.f32x2 %0, %1, %2;" : "=l"(d) : "l"(a), "l"(b));
    return d;
}
__device__ __forceinline__ u64 f2mul(u64 a, u64 b) {
    u64 d;
    asm("mul.rn.f32x2 %0, %1, %2;" : "=l"(d) : "l"(a), "l"(b));
    return d;
}
__device__ __forceinline__ u64 pk2(float lo, float hi) {
    u64 r;
    asm("mov.b64 %0, {%1, %2};" : "=l"(r) : "f"(lo), "f"(hi));
    return r;
}
__device__ __forceinline__ float2 unpk(u64 v) {
    float2 r;
    asm("mov.b64 {%0, %1}, %2;" : "=f"(r.x), "=f"(r.y) : "l"(v));
    return r;
}
__device__ __forceinline__ float foldp(u64 v) {
    float2 t = unpk(v);
    return t.x + t.y;
}
__device__ __forceinline__ float elu1(float x) {
    float r;
    asm("ex2.approx.ftz.f32 %0, %1;" : "=f"(r) : "f"(x * 1.4426950408889634f));
    return x > 0.0f ? x + 1.0f : r;
}

__global__ void __launch_bounds__(64, 6) linattn_kernel(
    const float* __restrict__ Q, const float* __restrict__ K,
    const float* __restrict__ V, float* __restrict__ O)
{
    __shared__ __align__(16) float sQ[HH * RP];   // 8704 B (stage-2 partial overlay)
    __shared__ __align__(16) float sK[HH * RP];   // 8704 B (stage-1 partial overlay)
    __shared__ __align__(16) float sV[HH * VP];   // 8192 B
    __shared__ __align__(16) float sA[HH * AP];   // 4608 B  -> total 30208 B

    const int tid = threadIdx.x;
    const int w   = tid >> 5;       // warp 0/1
    const int ln  = tid & 31;
    const size_t site = blockIdx.x;

    const float4* q4 = (const float4*)(Q + site * (HH * EE));
    const float4* k4 = (const float4*)(K + site * (HH * EE));
    const float4* v4 = (const float4*)(V + site * (HH * DD));

    // ---- Load + elu+1 (q,k), raw copy (v). 512 float4s, 64 threads. ----
    #pragma unroll
    for (int it = 0; it < 8; ++it) {
        int f  = tid + it * 64;       // 0..511
        int h  = f >> 4;
        int e4 = (f & 15) << 2;
        float4 a = q4[f];
        a.x = elu1(a.x); a.y = elu1(a.y); a.z = elu1(a.z); a.w = elu1(a.w);
        *(float4*)&sQ[h * RP + e4] = a;
        float4 b = k4[f];
        b.x = elu1(b.x); b.y = elu1(b.y); b.z = elu1(b.z); b.w = elu1(b.w);
        *(float4*)&sK[h * RP + e4] = b;
        *(float4*)&sV[h * VP + e4] = v4[f];
    }
    __syncthreads();                                  // bar0

    // ================= Stage 1: A = qf @ kf^T, split-K by warp =========
    // warp w covers e in [32w, 32w+32). Lane tile: rows {rg+8i}, cols {cg+4j}.
    {
        const int rg = ln & 7;
        const int cg = ln >> 3;
        const int eb = 32 * w;

        u64 acc[4][8];
        #pragma unroll
        for (int i = 0; i < 4; ++i)
            #pragma unroll
            for (int j = 0; j < 8; ++j) acc[i][j] = 0ULL;

        #pragma unroll
        for (int c = 0; c < 8; ++c) {
            int e0 = eb + 4 * c;
            ulonglong2 qv[4];
            #pragma unroll
            for (int i = 0; i < 4; ++i)
                qv[i] = *(const ulonglong2*)&sQ[(rg + 8 * i) * RP + e0];
            #pragma unroll
            for (int j = 0; j < 8; ++j) {
                ulonglong2 kv = *(const ulonglong2*)&sK[(cg + 4 * j) * RP + e0];
                #pragma unroll
                for (int i = 0; i < 4; ++i) {
                    acc[i][j] = f2fma(qv[i].x, kv.x, acc[i][j]);
                    acc[i][j] = f2fma(qv[i].y, kv.y, acc[i][j]);
                }
            }
        }
        __syncthreads();              // bar1: both warps done reading sQ/sK

        // w1 folds e-pairs and publishes 32 f32 partials into dead sK-space.
        float* sP1 = sK;              // pitch PF1 floats: 36*32*4 = 4608 <= 8704
        if (w == 1) {
            #pragma unroll
            for (int i = 0; i < 4; ++i) {
                float4 p0, p1;
                p0.x = foldp(acc[i][0]); p0.y = foldp(acc[i][1]);
                p0.z = foldp(acc[i][2]); p0.w = foldp(acc[i][3]);
                p1.x = foldp(acc[i][4]); p1.y = foldp(acc[i][5]);
                p1.z = foldp(acc[i][6]); p1.w = foldp(acc[i][7]);
                *(float4*)&sP1[ln * PF1 + i * 8]     = p0;
                *(float4*)&sP1[ln * PF1 + i * 8 + 4] = p1;
            }
        }
        __syncthreads();              // bar2: partials visible

        if (w == 0) {
            #pragma unroll
            for (int i = 0; i < 4; ++i) {
                int row = rg + 8 * i;
                float4 o0 = *(const float4*)&sP1[ln * PF1 + i * 8];
                float4 o1 = *(const float4*)&sP1[ln * PF1 + i * 8 + 4];
                sA[row * AP + cg]      = foldp(acc[i][0]) + o0.x;
                sA[row * AP + cg + 4]  = foldp(acc[i][1]) + o0.y;
                sA[row * AP + cg + 8]  = foldp(acc[i][2]) + o0.z;
                sA[row * AP + cg + 12] = foldp(acc[i][3]) + o0.w;
                sA[row * AP + cg + 16] = foldp(acc[i][4]) + o1.x;
                sA[row * AP + cg + 20] = foldp(acc[i][5]) + o1.y;
                sA[row * AP + cg + 24] = foldp(acc[i][6]) + o1.z;
                sA[row * AP + cg + 28] = foldp(acc[i][7]) + o1.w;
            }
        }
        __syncthreads();              // bar3: A complete
    }

    // ---- warp0 computes y[ln] (held in register; shfl'd at epilogue) ----
    float yv = 0.0f;
    if (w == 0) {
        const float4* ar = (const float4*)&sA[ln * AP];
        float s = 0.0f;
        #pragma unroll
        for (int j = 0; j < HH / 4; ++j) {
            float4 t = ar[j];
            s += (t.x + t.y) + (t.z + t.w);
        }
        yv = RSQRT_L / (s + EPSV);
    }

    // ================= Stage 2: X = A @ V, split-H' by warp ============
    // warp w covers h' in [16w, 16w+16). Lane tile: rows {rg2+4i} (8 rows),
    // d in {4dg..4dg+3} and {4dg+32..4dg+35}.
    {
        const int rg2 = ln & 3;
        const int dg  = ln >> 2;
        const int hb  = 16 * w;
        u64* sP2 = (u64*)sQ;          // dead sQ: pitch PU2 u64, 34*32*8 = 8704 B

        u64 xa[8][4];
        #pragma unroll
        for (int i = 0; i < 8; ++i)
            #pragma unroll
            for (int k = 0; k < 4; ++k) xa[i][k] = 0ULL;

        #pragma unroll
        for (int hc = 0; hc < 4; ++hc) {
            float4 av[8];
            #pragma unroll
            for (int i = 0; i < 8; ++i)
                av[i] = *(const float4*)&sA[(rg2 + 4 * i) * AP + hb + 4 * hc];
            #pragma unroll
            for (int u = 0; u < 4; ++u) {
                int hh = hb + 4 * hc + u;
                ulonglong2 v0 = *(const ulonglong2*)&sV[hh * VP + 4 * dg];
                ulonglong2 v1 = *(const ulonglong2*)&sV[hh * VP + 4 * dg + 32];
                #pragma unroll
                for (int i = 0; i < 8; ++i) {
                    float s  = (u == 0) ? av[i].x : (u == 1) ? av[i].y
                             : (u == 2) ? av[i].z : av[i].w;
                    u64 ps = pk2(s, s);
                    xa[i][0] = f2fma(ps, v0.x, xa[i][0]);
                    xa[i][1] = f2fma(ps, v0.y, xa[i][1]);
                    xa[i][2] = f2fma(ps, v1.x, xa[i][2]);
                    xa[i][3] = f2fma(ps, v1.y, xa[i][3]);
                }
            }
        }

        // w1 publishes all 32 u64 partials into dead sQ-space.
        // (sQ's last readers ran before bar1; no extra barrier needed here.)
        if (w == 1) {
            #pragma unroll
            for (int i = 0; i < 8; ++i) {
                *(ulonglong2*)&sP2[ln * PU2 + i * 4]     = *(ulonglong2*)&xa[i][0];
                *(ulonglong2*)&sP2[ln * PU2 + i * 4 + 2] = *(ulonglong2*)&xa[i][2];
            }
        }
        __syncthreads();              // bar4: stage-2 partials visible

        if (w == 0) {
            float* ob = O + site * (size_t)(HH * DD);
            #pragma unroll
            for (int i = 0; i < 8; ++i) {
                int row = rg2 + 4 * i;
                float yi = __shfl_sync(0xffffffffu, yv, row);
                u64 py = pk2(yi, yi);
                ulonglong2 oa  = *(const ulonglong2*)&sP2[ln * PU2 + i * 4];
                ulonglong2 obx = *(const ulonglong2*)&sP2[ln * PU2 + i * 4 + 2];
                ulonglong2 w0v, w1v;
                w0v.x = f2mul(f2add(xa[i][0], oa.x),  py);
                w0v.y = f2mul(f2add(xa[i][1], oa.y),  py);
                w1v.x = f2mul(f2add(xa[i][2], obx.x), py);
                w1v.y = f2mul(f2add(xa[i][3], obx.y), py);
                *(ulonglong2*)(ob + row * DD + 4 * dg)      = w0v;
                *(ulonglong2*)(ob + row * DD + 4 * dg + 32) = w1v;
            }
        }
    }
}

extern "C" void kernel_launch(void* const* d_in, const int* in_sizes, int n_in,
                              void* d_out, int out_size) {
    const float* Q = (const float*)d_in[0];
    const float* K = (const float*)d_in[1];
    const float* V = (const float*)d_in[2];
    float* O = (float*)d_out;
    int nsites = in_sizes[0] / (HH * EE);   // B*L = 16384
    linattn_kernel<<<nsites, 64>>>(Q, K, V, O);
}

// round 7
// speedup vs baseline: 1.6600x; 1.0128x over previous
#include <cuda_runtime.h>
#include <cstdint>

// LinearAttention per (b,l) site (16384 sites):
//   qf=elu(q)+1, kf=elu(k)+1 [32,64]; A = qf@kf^T [32,32];
//   y[h] = L^-0.5/(rowsum(A)+eps); x = diag(y) A V [32,64].
// R7 = R6 + (a) V staged via cp.async.bulk on the TMA port (removes V's
//     LDG+STS l1tex wavefronts; sV pitch 64 makes the site's V a bit-exact
//     contiguous 8KB copy), (b) y folded into A during stage-1 finalize
//     (rowsum via shfl_xor from in-register f[], removes y pass + epilogue
//     scaling). Keeps R6's 144-reg / 7-CTA configuration.

#define HH 32
#define EE 64
#define DD 64
#define RP 68       // q/k pitch (272B): stage-1 row accesses conflict-free
#define VP 64       // v pitch (256B): contiguous copy of site V; stage-2 conflict-free
#define AP 36       // A pitch (144B)
#define PF1 36      // stage-1 partial pitch in sK-space (floats)
#define PU2 34      // stage-2 partial pitch in sQ-space (u64)
#define EPSV 1e-6f
#define RSQRT_L 0.022097086912079608f   // 2048^-0.5

typedef unsigned long long u64;

__device__ __forceinline__ u64 f2fma(u64 a, u64 b, u64 c) {
    u64 d;
    asm("fma.rn.f32x2 %0, %1, %2, %3;" : "=l"(d) : "l"(a), "l"(b), "l"(c));
    return d;
}
__device__ __forceinline__ u64 f2add(u64 a, u64 b) {
    u64 d;
    asm("add.rn.f32x2 %0, %1, %2;" : "=l"(d) : "l"(a), "l"(b));
    return d;
}
__device__ __forceinline__ u64 pk2(float lo, float hi) {
    u64 r;
    asm("mov.b64 %0, {%1, %2};" : "=l"(r) : "f"(lo), "f"(hi));
    return r;
}
__device__ __forceinline__ float2 unpk(u64 v) {
    float2 r;
    asm("mov.b64 {%0, %1}, %2;" : "=f"(r.x), "=f"(r.y) : "l"(v));
    return r;
}
__device__ __forceinline__ float foldp(u64 v) {
    float2 t = unpk(v);
    return t.x + t.y;
}
__device__ __forceinline__ float elu1(float x) {
    float r;
    asm("ex2.approx.ftz.f32 %0, %1;" : "=f"(r) : "f"(x * 1.4426950408889634f));
    return x > 0.0f ? x + 1.0f : r;
}
__device__ __forceinline__ uint32_t smem_u32(const void* p) {
    uint32_t a;
    asm("{ .reg .u64 t; cvta.to.shared.u64 t, %1; cvt.u32.u64 %0, t; }"
        : "=r"(a) : "l"(p));
    return a;
}

__global__ void __launch_bounds__(64, 6) linattn_kernel(
    const float* __restrict__ Q, const float* __restrict__ K,
    const float* __restrict__ V, float* __restrict__ O)
{
    __shared__ __align__(16)  float sQ[HH * RP];   // 8704 B (stage-2 partial overlay)
    __shared__ __align__(16)  float sK[HH * RP];   // 8704 B (stage-1 partial overlay)
    __shared__ __align__(128) float sV[HH * VP];   // 8192 B (bulk-copy target)
    __shared__ __align__(16)  float sA[HH * AP];   // 4608 B
    __shared__ __align__(8)   u64   mbarV;         // mbarrier for V bulk copy

    const int tid = threadIdx.x;
    const int w   = tid >> 5;       // warp 0/1
    const int ln  = tid & 31;
    const size_t site = blockIdx.x;

    const float4* q4 = (const float4*)(Q + site * (HH * EE));
    const float4* k4 = (const float4*)(K + site * (HH * EE));
    const float*  vg = V + site * (HH * DD);

    // ---- Kick off V copy on the TMA/bulk port (8192B, contiguous). ----
    const uint32_t mb = smem_u32(&mbarV);
    if (tid == 0) {
        asm volatile("mbarrier.init.shared.b64 [%0], %1;"
                     :: "r"(mb), "r"(1) : "memory");
        asm volatile("fence.proxy.async.shared::cta;" ::: "memory");
        asm volatile("mbarrier.arrive.expect_tx.shared.b64 _, [%0], %1;"
                     :: "r"(mb), "r"(8192u) : "memory");
        asm volatile(
            "cp.async.bulk.shared::cta.global.mbarrier::complete_tx::bytes "
            "[%0], [%1], %2, [%3];"
            :: "r"(smem_u32(sV)), "l"(vg), "r"(8192u), "r"(mb) : "memory");
    }

    // ---- Load + elu+1 (q,k). 256 float4s, 64 threads. ----
    #pragma unroll
    for (int it = 0; it < 8; ++it) {
        int f  = tid + it * 64;       // 0..511
        int h  = f >> 4;
        int e4 = (f & 15) << 2;
        float4 a = q4[f];
        a.x = elu1(a.x); a.y = elu1(a.y); a.z = elu1(a.z); a.w = elu1(a.w);
        *(float4*)&sQ[h * RP + e4] = a;
        float4 b = k4[f];
        b.x = elu1(b.x); b.y = elu1(b.y); b.z = elu1(b.z); b.w = elu1(b.w);
        *(float4*)&sK[h * RP + e4] = b;
    }
    __syncthreads();                                  // bar0

    // ================= Stage 1: A = qf @ kf^T, split-K by warp =========
    // warp w covers e in [32w, 32w+32). Lane tile: rows {rg+8i}, cols {cg+4j}.
    {
        const int rg = ln & 7;
        const int cg = ln >> 3;
        const int eb = 32 * w;

        u64 acc[4][8];
        #pragma unroll
        for (int i = 0; i < 4; ++i)
            #pragma unroll
            for (int j = 0; j < 8; ++j) acc[i][j] = 0ULL;

        #pragma unroll
        for (int c = 0; c < 8; ++c) {
            int e0 = eb + 4 * c;
            ulonglong2 qv[4];
            #pragma unroll
            for (int i = 0; i < 4; ++i)
                qv[i] = *(const ulonglong2*)&sQ[(rg + 8 * i) * RP + e0];
            #pragma unroll
            for (int j = 0; j < 8; ++j) {
                ulonglong2 kv = *(const ulonglong2*)&sK[(cg + 4 * j) * RP + e0];
                #pragma unroll
                for (int i = 0; i < 4; ++i) {
                    acc[i][j] = f2fma(qv[i].x, kv.x, acc[i][j]);
                    acc[i][j] = f2fma(qv[i].y, kv.y, acc[i][j]);
                }
            }
        }
        __syncthreads();              // bar1: both warps done reading sQ/sK

        // w1 folds e-pairs and publishes 32 f32 partials into dead sK-space.
        float* sP1 = sK;              // pitch PF1 floats
        if (w == 1) {
            #pragma unroll
            for (int i = 0; i < 4; ++i) {
                float4 p0, p1;
                p0.x = foldp(acc[i][0]); p0.y = foldp(acc[i][1]);
                p0.z = foldp(acc[i][2]); p0.w = foldp(acc[i][3]);
                p1.x = foldp(acc[i][4]); p1.y = foldp(acc[i][5]);
                p1.z = foldp(acc[i][6]); p1.w = foldp(acc[i][7]);
                *(float4*)&sP1[ln * PF1 + i * 8]     = p0;
                *(float4*)&sP1[ln * PF1 + i * 8 + 4] = p1;
            }
        }
        __syncthreads();              // bar2: partials visible

        // w0 finalizes; rowsum via shfl over lanes {ln^8, ln^16} (same rg,
        // all 4 cg groups); writes y-scaled A rows.
        if (w == 0) {
            #pragma unroll
            for (int i = 0; i < 4; ++i) {
                int row = rg + 8 * i;
                float4 o0 = *(const float4*)&sP1[ln * PF1 + i * 8];
                float4 o1 = *(const float4*)&sP1[ln * PF1 + i * 8 + 4];
                float f0 = foldp(acc[i][0]) + o0.x;
                float f1 = foldp(acc[i][1]) + o0.y;
                float f2 = foldp(acc[i][2]) + o0.z;
                float f3 = foldp(acc[i][3]) + o0.w;
                float f4 = foldp(acc[i][4]) + o1.x;
                float f5 = foldp(acc[i][5]) + o1.y;
                float f6 = foldp(acc[i][6]) + o1.z;
                float f7 = foldp(acc[i][7]) + o1.w;
                float s = ((f0 + f1) + (f2 + f3)) + ((f4 + f5) + (f6 + f7));
                s += __shfl_xor_sync(0xffffffffu, s, 8);
                s += __shfl_xor_sync(0xffffffffu, s, 16);
                float y = RSQRT_L / (s + EPSV);
                sA[row * AP + cg]      = y * f0;
                sA[row * AP + cg + 4]  = y * f1;
                sA[row * AP + cg + 8]  = y * f2;
                sA[row * AP + cg + 12] = y * f3;
                sA[row * AP + cg + 16] = y * f4;
                sA[row * AP + cg + 20] = y * f5;
                sA[row * AP + cg + 24] = y * f6;
                sA[row * AP + cg + 28] = y * f7;
            }
        }
        __syncthreads();              // bar3: y-scaled A complete
    }

    // ---- ensure V bulk copy has landed before stage-2 reads sV ----
    {
        uint32_t done;
        asm volatile(
            "{\n\t"
            ".reg .pred p;\n\t"
            "mbarrier.try_wait.parity.acquire.cta.shared::cta.b64 p, [%1], %2;\n\t"
            "selp.b32 %0, 1, 0, p;\n\t"
            "}"
            : "=r"(done) : "r"(mb), "r"(0u) : "memory");
        if (!done) {
            asm volatile(
                "{\n\t"
                ".reg .pred P1;\n\t"
                "WL_%=:\n\t"
                "mbarrier.try_wait.parity.acquire.cta.shared::cta.b64 P1, [%0], %1, 0x989680;\n\t"
                "@P1 bra.uni WD_%=;\n\t"
                "bra.uni WL_%=;\n\t"
                "WD_%=:\n\t"
                "}"
                :: "r"(mb), "r"(0u) : "memory");
        }
    }

    // ================= Stage 2: X = A' @ V, split-H' by warp ============
    // warp w covers h' in [16w, 16w+16). Lane tile: rows {rg2+4i} (8 rows),
    // d in {4dg..4dg+3} and {4dg+32..4dg+35}.
    {
        const int rg2 = ln & 3;
        const int dg  = ln >> 2;
        const int hb  = 16 * w;
        u64* sP2 = (u64*)sQ;          // dead sQ: pitch PU2 u64

        u64 xa[8][4];
        #pragma unroll
        for (int i = 0; i < 8; ++i)
            #pragma unroll
            for (int k = 0; k < 4; ++k) xa[i][k] = 0ULL;

        #pragma unroll
        for (int hc = 0; hc < 4; ++hc) {
            float4 av[8];
            #pragma unroll
            for (int i = 0; i < 8; ++i)
                av[i] = *(const float4*)&sA[(rg2 + 4 * i) * AP + hb + 4 * hc];
            #pragma unroll
            for (int u = 0; u < 4; ++u) {
                int hh = hb + 4 * hc + u;
                ulonglong2 v0 = *(const ulonglong2*)&sV[hh * VP + 4 * dg];
                ulonglong2 v1 = *(const ulonglong2*)&sV[hh * VP + 4 * dg + 32];
                #pragma unroll
                for (int i = 0; i < 8; ++i) {
                    float s  = (u == 0) ? av[i].x : (u == 1) ? av[i].y
                             : (u == 2) ? av[i].z : av[i].w;
                    u64 ps = pk2(s, s);
                    xa[i][0] = f2fma(ps, v0.x, xa[i][0]);
                    xa[i][1] = f2fma(ps, v0.y, xa[i][1]);
                    xa[i][2] = f2fma(ps, v1.x, xa[i][2]);
                    xa[i][3] = f2fma(ps, v1.y, xa[i][3]);
                }
            }
        }

        // w1 publishes all 32 u64 partials into dead sQ-space.
        if (w == 1) {
            #pragma unroll
            for (int i = 0; i < 8; ++i) {
                *(ulonglong2*)&sP2[ln * PU2 + i * 4]     = *(ulonglong2*)&xa[i][0];
                *(ulonglong2*)&sP2[ln * PU2 + i * 4 + 2] = *(ulonglong2*)&xa[i][2];
            }
        }
        __syncthreads();              // bar4: stage-2 partials visible

        if (w == 0) {
            float* ob = O + site * (size_t)(HH * DD);
            #pragma unroll
            for (int i = 0; i < 8; ++i) {
                int row = rg2 + 4 * i;
                ulonglong2 oa  = *(const ulonglong2*)&sP2[ln * PU2 + i * 4];
                ulonglong2 obx = *(const ulonglong2*)&sP2[ln * PU2 + i * 4 + 2];
                ulonglong2 w0v, w1v;
                w0v.x = f2add(xa[i][0], oa.x);
                w0v.y = f2add(xa[i][1], oa.y);
                w1v.x = f2add(xa[i][2], obx.x);
                w1v.y = f2add(xa[i][3], obx.y);
                *(ulonglong2*)(ob + row * DD + 4 * dg)      = w0v;
                *(ulonglong2*)(ob + row * DD + 4 * dg + 32) = w1v;
            }
        }
    }
}

extern "C" void kernel_launch(void* const* d_in, const int* in_sizes, int n_in,
                              void* d_out, int out_size) {
    const float* Q = (const float*)d_in[0];
    const float* K = (const float*)d_in[1];
    const float* V = (const float*)d_in[2];
    float* O = (float*)d_out;
    int nsites = in_sizes[0] / (HH * EE);   // B*L = 16384
    linattn_kernel<<<nsites, 64>>>(Q, K, V, O);
}